// round 14
// baseline (speedup 1.0000x reference)
#include <cuda_runtime.h>
#include <math.h>

#define SQ3    1.7320508075688772f
#define IS3    0.57735026918962576451f
#define HI_CLIP (0.99990f * SQ3)

// ---------------------------------------------------------------------------
// Hot-path eval: u = xc - 1 (common center), 3-level FSEL binary search ->
// byte offset (SEL/SEL/SEL + LOP3) -> conflict-free 8-entry LDS.128 -> Horner.
// ---------------------------------------------------------------------------
__device__ __forceinline__ float eval_spline(float xv,
                                             float r1, float r2, float r3, float r4,
                                             float r5, float r6, float r7,
                                             const char* __restrict__ coef_base)
{
    float xc = fminf(xv, HI_CLIP);            // inputs >= 0
    float u  = xc - 1.0f;                     // common center; parallel to tree
    bool  b2 = xc >= r4;
    float p1 = b2 ? r6 : r2;
    float q1 = b2 ? r5 : r1;                  // depends only on b2
    float q2 = b2 ? r7 : r3;
    bool  b1 = xc >= p1;
    float p0 = b1 ? q2 : q1;
    bool  b0 = xc >= p0;
    int off = (b2 ? 64 : 0) | (b1 ? 32 : 0) | (b0 ? 16 : 0);
    float4 cf = *(const float4*)(coef_base + off);   // 8 x 16B = 128B: conflict-free
    return fmaf(fmaf(fmaf(cf.w, u, cf.z), u, cf.y), u, cf.x);
}

// ---------------------------------------------------------------------------
// Single fused persistent kernel, 6 CTAs/SM. Prologue per CTA (float-only):
// stage weights -> tiny MLP -> softmax/cumsum knots -> symbolic de Boor ->
// float Taylor shift to common center x=1 -> shared coef table.
// Main loop: 4 front-batched float4 loads per thread (MLP=4), then 16
// independent scalar evals, then 4 streaming stores.
// ---------------------------------------------------------------------------
__global__ __launch_bounds__(256, 6) void fused_spline_kernel(
        const float* __restrict__ x, float* __restrict__ y, int n,
        const float* __restrict__ a,
        const float* __restrict__ W1, const float* __restrict__ b1,
        const float* __restrict__ W2, const float* __restrict__ b2,
        const float* __restrict__ Ww, const float* __restrict__ bw,
        const float* __restrict__ Wk, const float* __restrict__ bk)
{
    __shared__ float sA[1], sW1[16], sB1[16], sW2[256], sB2[16];
    __shared__ float sWW[144], sBW[9], sWK[112], sBK[7];
    __shared__ float n1[16], n2[16], w9[9], kl7[7];
    __shared__ float t[14], c[10], knx[8];
    __shared__ float4 s_coef[8];          // conflict-free LDS.128 table

    int tid = threadIdx.x;

    // ---- stage all 577 weight scalars (one parallel load round) ----
    if (tid == 0) sA[0] = a[0];
    if (tid < 16) { sW1[tid] = W1[tid]; sB1[tid] = b1[tid]; sB2[tid] = b2[tid]; }
    sW2[tid] = W2[tid];
    if (tid < 144) sWW[tid] = Ww[tid];
    if (tid < 112) sWK[tid] = Wk[tid];
    if (tid >= 128 && tid < 137) sBW[tid - 128] = bw[tid - 128];
    if (tid >= 160 && tid < 167) sBK[tid - 160] = bk[tid - 160];
    __syncthreads();

    // ---- layer 1 ----
    if (tid < 16) n1[tid] = sinf(sA[0] * sW1[tid] + sB1[tid]);
    __syncthreads();

    // ---- layer 2 ----
    if (tid < 16) {
        float s = sB2[tid];
        #pragma unroll
        for (int j = 0; j < 16; j++) s += n1[j] * sW2[j * 16 + tid];
        n2[tid] = sinf(s);
    }
    __syncthreads();

    // ---- heads (two warps in parallel) ----
    if (tid < 9) {
        float s = sBW[tid];
        #pragma unroll
        for (int j = 0; j < 16; j++) s += n2[j] * sWW[j * 9 + tid];
        w9[tid] = s;
    }
    if (tid >= 32 && tid < 39) {
        int m = tid - 32;
        float s = sBK[m];
        #pragma unroll
        for (int j = 0; j < 16; j++) s += n2[j] * sWK[j * 7 + m];
        kl7[m] = s;
    }
    __syncthreads();

    // ---- softmax + cumsum -> knots; padded knot vector & control points ----
    if (tid == 0) {
        float mx = kl7[0];
        #pragma unroll
        for (int m = 1; m < 7; m++) mx = fmaxf(mx, kl7[m]);
        float e[7], ssum = 0.f;
        #pragma unroll
        for (int m = 0; m < 7; m++) { e[m] = expf(kl7[m] - mx); ssum += e[m]; }
        float inv = 1.f / ssum;
        float kk[8]; kk[0] = 0.f;
        float cum = 0.f;
        #pragma unroll
        for (int m = 0; m < 7; m++) { cum += e[m] * inv; kk[m + 1] = cum; }

        t[0] = t[1] = t[2] = 0.f;
        #pragma unroll
        for (int m = 0; m < 8; m++) { t[3 + m] = kk[m]; knx[m] = kk[m] * SQ3; }
        t[11] = t[12] = t[13] = 1.f;
        c[0] = 0.f;
        #pragma unroll
        for (int m = 0; m < 9; m++) c[1 + m] = w9[m];
    }
    __syncthreads();

    // ---- symbolic de Boor per interval (threads 0..7, knot index k = 3..10) ----
    if (tid < 8) {
        int k = tid + 3;
        float tkn = t[k];
        float d[4][4];   // d[j][m]: coefficient of u^m (normalized space)
        #pragma unroll
        for (int j = 0; j < 4; j++) {
            int ci = k + j - 3; if (ci > 9) ci = 9;   // JAX clip-mode gather
            d[j][0] = c[ci]; d[j][1] = d[j][2] = d[j][3] = 0.f;
        }
        #pragma unroll
        for (int r = 1; r <= 3; r++) {
            #pragma unroll
            for (int j = 3; j >= 1; j--) {
                if (j < r) continue;
                float lo = t[k + j - 3];
                float hi = t[k + j + 1 - r];
                float dt = hi - lo;
                float invd = (dt > 0.f) ? (1.f / dt) : 0.f;   // guard empty tail interval
                float a0 = (tkn - lo) * invd;                 // alpha(u) = a0 + invd*u
                float em1 = 0.f;
                float nd[4];
                #pragma unroll
                for (int m = 0; m < 4; m++) {
                    float ee = d[j][m] - d[j - 1][m];
                    nd[m] = d[j - 1][m] + a0 * ee + invd * em1;
                    em1 = ee;
                }
                #pragma unroll
                for (int m = 0; m < 4; m++) d[j][m] = nd[m];
            }
        }
        // x-space coeffs about the interval knot, then FLOAT Taylor shift to
        // common center x = 1.
        float a0 = d[3][0];
        float a1 = d[3][1] * IS3;
        float a2 = d[3][2] * (IS3 * IS3);
        float a3 = d[3][3] * (IS3 * IS3 * IS3);
        float s  = fmaf(-tkn, SQ3, 1.0f);          // center - left_knot_x
        float b3f = a3;
        float b2f = fmaf(3.0f * a3, s, a2);
        float b1f = fmaf(fmaf(3.0f * a3, s, 2.0f * a2), s, a1);
        float b0f = fmaf(fmaf(fmaf(a3, s, a2), s, a1), s, a0);
        s_coef[tid] = make_float4(b0f, b1f, b2f, b3f);
    }
    __syncthreads();

    // interior knots (x-space) in registers for the binary search
    const float r1 = knx[1], r2 = knx[2], r3 = knx[3], r4 = knx[4];
    const float r5 = knx[5], r6 = knx[6], r7 = knx[7];
    const char* coef_base = (const char*)s_coef;

    // ---- main streaming loop: 4 float4 per thread per iteration (MLP=4) ----
    int n4 = n >> 2;
    const float4* __restrict__ xin  = (const float4*)x;
    float4* __restrict__       yout = (float4*)y;
    int step = gridDim.x * 1024;

    for (int base = blockIdx.x * 1024 + tid; base < n4; base += step) {
        int i1 = base + 256;
        int i2 = base + 512;
        int i3 = base + 768;
        bool p1 = i1 < n4, p2 = i2 < n4, p3 = i3 < n4;

        // front-batched loads
        float4 v0 = xin[base];
        float4 v1, v2, v3;
        if (p1) v1 = xin[i1];
        if (p2) v2 = xin[i2];
        if (p3) v3 = xin[i3];

        float4 o0;
        o0.x = eval_spline(v0.x, r1,r2,r3,r4,r5,r6,r7, coef_base);
        o0.y = eval_spline(v0.y, r1,r2,r3,r4,r5,r6,r7, coef_base);
        o0.z = eval_spline(v0.z, r1,r2,r3,r4,r5,r6,r7, coef_base);
        o0.w = eval_spline(v0.w, r1,r2,r3,r4,r5,r6,r7, coef_base);
        __stcs(yout + base, o0);

        if (p1) {
            float4 o1;
            o1.x = eval_spline(v1.x, r1,r2,r3,r4,r5,r6,r7, coef_base);
            o1.y = eval_spline(v1.y, r1,r2,r3,r4,r5,r6,r7, coef_base);
            o1.z = eval_spline(v1.z, r1,r2,r3,r4,r5,r6,r7, coef_base);
            o1.w = eval_spline(v1.w, r1,r2,r3,r4,r5,r6,r7, coef_base);
            __stcs(yout + i1, o1);
        }
        if (p2) {
            float4 o2;
            o2.x = eval_spline(v2.x, r1,r2,r3,r4,r5,r6,r7, coef_base);
            o2.y = eval_spline(v2.y, r1,r2,r3,r4,r5,r6,r7, coef_base);
            o2.z = eval_spline(v2.z, r1,r2,r3,r4,r5,r6,r7, coef_base);
            o2.w = eval_spline(v2.w, r1,r2,r3,r4,r5,r6,r7, coef_base);
            __stcs(yout + i2, o2);
        }
        if (p3) {
            float4 o3;
            o3.x = eval_spline(v3.x, r1,r2,r3,r4,r5,r6,r7, coef_base);
            o3.y = eval_spline(v3.y, r1,r2,r3,r4,r5,r6,r7, coef_base);
            o3.z = eval_spline(v3.z, r1,r2,r3,r4,r5,r6,r7, coef_base);
            o3.w = eval_spline(v3.w, r1,r2,r3,r4,r5,r6,r7, coef_base);
            __stcs(yout + i3, o3);
        }
    }

    // ---- scalar tail (n % 4), handled by block 0 ----
    int rem = n - (n4 << 2);
    if (rem > 0 && blockIdx.x == 0 && tid < rem) {
        int i = (n4 << 2) + tid;
        y[i] = eval_spline(x[i], r1,r2,r3,r4,r5,r6,r7, coef_base);
    }
}

extern "C" void kernel_launch(void* const* d_in, const int* in_sizes, int n_in,
                              void* d_out, int out_size)
{
    const float* x  = (const float*)d_in[0];
    const float* a  = (const float*)d_in[1];
    const float* W1 = (const float*)d_in[2];
    const float* b1 = (const float*)d_in[3];
    const float* W2 = (const float*)d_in[4];
    const float* b2 = (const float*)d_in[5];
    const float* Ww = (const float*)d_in[6];
    const float* bw = (const float*)d_in[7];
    const float* Wk = (const float*)d_in[8];
    const float* bk = (const float*)d_in[9];
    float* out = (float*)d_out;

    int n  = out_size;
    int n4 = n >> 2;
    int blocks = 148 * 6;                      // persistent, 6 CTAs/SM
    int needed = (n4 + 1023) / 1024;
    if (needed < 1) needed = 1;
    if (blocks > needed) blocks = needed;

    fused_spline_kernel<<<blocks, 256>>>(x, out, n,
                                         a, W1, b1, W2, b2, Ww, bw, Wk, bk);
}

// round 15
// speedup vs baseline: 1.2076x; 1.2076x over previous
#include <cuda_runtime.h>
#include <math.h>

#define SQ3    1.7320508075688772f
#define IS3    0.57735026918962576451f
#define HI_CLIP (0.99990f * SQ3)

// ---------------------------------------------------------------------------
// Hot-path eval: u = xc - 1 (common center), 3-level FSEL binary search with
// POINTER selects (no offset OR-combine) -> conflict-free 8-entry LDS.128 ->
// Horner.
// ---------------------------------------------------------------------------
__device__ __forceinline__ float eval_spline(float xv,
                                             float r1, float r2, float r3, float r4,
                                             float r5, float r6, float r7,
                                             const char* __restrict__ coef_base)
{
    float xc = fminf(xv, HI_CLIP);            // inputs >= 0
    float u  = xc - 1.0f;                     // common center; parallel to tree
    bool  b2 = xc >= r4;
    float p1 = b2 ? r6 : r2;
    float q1 = b2 ? r5 : r1;                  // depends only on b2
    float q2 = b2 ? r7 : r3;
    const char* a2p = b2 ? coef_base + 64 : coef_base;
    bool  b1 = xc >= p1;
    float p0 = b1 ? q2 : q1;
    const char* a1p = b1 ? a2p + 32 : a2p;
    bool  b0 = xc >= p0;
    const char* a0p = b0 ? a1p + 16 : a1p;
    float4 cf = *(const float4*)a0p;          // 8 x 16B = 128B: conflict-free
    return fmaf(fmaf(fmaf(cf.w, u, cf.z), u, cf.y), u, cf.x);
}

// ---------------------------------------------------------------------------
// Single fused persistent kernel (8 CTAs/SM, regs ~32). Prologue per CTA
// (float-only): stage weights -> tiny MLP -> softmax/cumsum knots -> symbolic
// de Boor -> float Taylor shift to common center x=1 -> shared coef table.
// Main loop over the 512-aligned region: NO inner predicates (proof: tile
// starts are 512-aligned, tid < 256 => base+256 < main_n4). Tail via block 0.
// ---------------------------------------------------------------------------
__global__ __launch_bounds__(256) void fused_spline_kernel(
        const float* __restrict__ x, float* __restrict__ y, int n,
        const float* __restrict__ a,
        const float* __restrict__ W1, const float* __restrict__ b1,
        const float* __restrict__ W2, const float* __restrict__ b2,
        const float* __restrict__ Ww, const float* __restrict__ bw,
        const float* __restrict__ Wk, const float* __restrict__ bk)
{
    __shared__ float sA[1], sW1[16], sB1[16], sW2[256], sB2[16];
    __shared__ float sWW[144], sBW[9], sWK[112], sBK[7];
    __shared__ float n1[16], n2[16], w9[9], kl7[7];
    __shared__ float t[14], c[10], knx[8];
    __shared__ float4 s_coef[8];          // conflict-free LDS.128 table

    int tid = threadIdx.x;

    // ---- stage all 577 weight scalars (one parallel load round) ----
    if (tid == 0) sA[0] = a[0];
    if (tid < 16) { sW1[tid] = W1[tid]; sB1[tid] = b1[tid]; sB2[tid] = b2[tid]; }
    sW2[tid] = W2[tid];
    if (tid < 144) sWW[tid] = Ww[tid];
    if (tid < 112) sWK[tid] = Wk[tid];
    if (tid >= 128 && tid < 137) sBW[tid - 128] = bw[tid - 128];
    if (tid >= 160 && tid < 167) sBK[tid - 160] = bk[tid - 160];
    __syncthreads();

    // ---- layer 1 ----
    if (tid < 16) n1[tid] = sinf(sA[0] * sW1[tid] + sB1[tid]);
    __syncthreads();

    // ---- layer 2 ----
    if (tid < 16) {
        float s = sB2[tid];
        #pragma unroll
        for (int j = 0; j < 16; j++) s += n1[j] * sW2[j * 16 + tid];
        n2[tid] = sinf(s);
    }
    __syncthreads();

    // ---- heads (two warps in parallel) ----
    if (tid < 9) {
        float s = sBW[tid];
        #pragma unroll
        for (int j = 0; j < 16; j++) s += n2[j] * sWW[j * 9 + tid];
        w9[tid] = s;
    }
    if (tid >= 32 && tid < 39) {
        int m = tid - 32;
        float s = sBK[m];
        #pragma unroll
        for (int j = 0; j < 16; j++) s += n2[j] * sWK[j * 7 + m];
        kl7[m] = s;
    }
    __syncthreads();

    // ---- softmax + cumsum -> knots; padded knot vector & control points ----
    if (tid == 0) {
        float mx = kl7[0];
        #pragma unroll
        for (int m = 1; m < 7; m++) mx = fmaxf(mx, kl7[m]);
        float e[7], ssum = 0.f;
        #pragma unroll
        for (int m = 0; m < 7; m++) { e[m] = expf(kl7[m] - mx); ssum += e[m]; }
        float inv = 1.f / ssum;
        float kk[8]; kk[0] = 0.f;
        float cum = 0.f;
        #pragma unroll
        for (int m = 0; m < 7; m++) { cum += e[m] * inv; kk[m + 1] = cum; }

        t[0] = t[1] = t[2] = 0.f;
        #pragma unroll
        for (int m = 0; m < 8; m++) { t[3 + m] = kk[m]; knx[m] = kk[m] * SQ3; }
        t[11] = t[12] = t[13] = 1.f;
        c[0] = 0.f;
        #pragma unroll
        for (int m = 0; m < 9; m++) c[1 + m] = w9[m];
    }
    __syncthreads();

    // ---- symbolic de Boor per interval (threads 0..7, knot index k = 3..10) ----
    if (tid < 8) {
        int k = tid + 3;
        float tkn = t[k];
        float d[4][4];   // d[j][m]: coefficient of u^m (normalized space)
        #pragma unroll
        for (int j = 0; j < 4; j++) {
            int ci = k + j - 3; if (ci > 9) ci = 9;   // JAX clip-mode gather
            d[j][0] = c[ci]; d[j][1] = d[j][2] = d[j][3] = 0.f;
        }
        #pragma unroll
        for (int r = 1; r <= 3; r++) {
            #pragma unroll
            for (int j = 3; j >= 1; j--) {
                if (j < r) continue;
                float lo = t[k + j - 3];
                float hi = t[k + j + 1 - r];
                float dt = hi - lo;
                float invd = (dt > 0.f) ? (1.f / dt) : 0.f;   // guard empty tail interval
                float a0 = (tkn - lo) * invd;                 // alpha(u) = a0 + invd*u
                float em1 = 0.f;
                float nd[4];
                #pragma unroll
                for (int m = 0; m < 4; m++) {
                    float ee = d[j][m] - d[j - 1][m];
                    nd[m] = d[j - 1][m] + a0 * ee + invd * em1;
                    em1 = ee;
                }
                #pragma unroll
                for (int m = 0; m < 4; m++) d[j][m] = nd[m];
            }
        }
        // x-space coeffs about the interval knot, then FLOAT Taylor shift to
        // common center x = 1.
        float a0 = d[3][0];
        float a1 = d[3][1] * IS3;
        float a2 = d[3][2] * (IS3 * IS3);
        float a3 = d[3][3] * (IS3 * IS3 * IS3);
        float s  = fmaf(-tkn, SQ3, 1.0f);          // center - left_knot_x
        float b3f = a3;
        float b2f = fmaf(3.0f * a3, s, a2);
        float b1f = fmaf(fmaf(3.0f * a3, s, 2.0f * a2), s, a1);
        float b0f = fmaf(fmaf(fmaf(a3, s, a2), s, a1), s, a0);
        s_coef[tid] = make_float4(b0f, b1f, b2f, b3f);
    }
    __syncthreads();

    // interior knots (x-space) in registers for the binary search
    const float r1 = knx[1], r2 = knx[2], r3 = knx[3], r4 = knx[4];
    const float r5 = knx[5], r6 = knx[6], r7 = knx[7];
    const char* coef_base = (const char*)s_coef;

    // ---- main streaming loop over 512-aligned region: NO predicates ----
    int n4 = n >> 2;
    int main_n4 = n4 & ~511;              // multiple of 512 float4s
    const float4* __restrict__ xin  = (const float4*)x;
    float4* __restrict__       yout = (float4*)y;
    int step = gridDim.x * 512;

    for (int base = blockIdx.x * 512 + tid; base < main_n4; base += step) {
        int i1 = base + 256;              // provably < main_n4

        float4 v0 = xin[base];            // default caching: L2-resident across replays
        float4 v1 = xin[i1];

        float4 o0;
        o0.x = eval_spline(v0.x, r1,r2,r3,r4,r5,r6,r7, coef_base);
        o0.y = eval_spline(v0.y, r1,r2,r3,r4,r5,r6,r7, coef_base);
        o0.z = eval_spline(v0.z, r1,r2,r3,r4,r5,r6,r7, coef_base);
        o0.w = eval_spline(v0.w, r1,r2,r3,r4,r5,r6,r7, coef_base);
        __stcs(yout + base, o0);          // streaming store: don't thrash L2

        float4 o1;
        o1.x = eval_spline(v1.x, r1,r2,r3,r4,r5,r6,r7, coef_base);
        o1.y = eval_spline(v1.y, r1,r2,r3,r4,r5,r6,r7, coef_base);
        o1.z = eval_spline(v1.z, r1,r2,r3,r4,r5,r6,r7, coef_base);
        o1.w = eval_spline(v1.w, r1,r2,r3,r4,r5,r6,r7, coef_base);
        __stcs(yout + i1, o1);
    }

    // ---- tail: remaining float4s [main_n4, n4) + scalar rem, block 0 ----
    if (blockIdx.x == 0) {
        for (int i = main_n4 + tid; i < n4; i += 256) {
            float4 v = xin[i];
            float4 o;
            o.x = eval_spline(v.x, r1,r2,r3,r4,r5,r6,r7, coef_base);
            o.y = eval_spline(v.y, r1,r2,r3,r4,r5,r6,r7, coef_base);
            o.z = eval_spline(v.z, r1,r2,r3,r4,r5,r6,r7, coef_base);
            o.w = eval_spline(v.w, r1,r2,r3,r4,r5,r6,r7, coef_base);
            yout[i] = o;
        }
        int rem = n - (n4 << 2);
        if (tid < rem) {
            int i = (n4 << 2) + tid;
            y[i] = eval_spline(x[i], r1,r2,r3,r4,r5,r6,r7, coef_base);
        }
    }
}

extern "C" void kernel_launch(void* const* d_in, const int* in_sizes, int n_in,
                              void* d_out, int out_size)
{
    const float* x  = (const float*)d_in[0];
    const float* a  = (const float*)d_in[1];
    const float* W1 = (const float*)d_in[2];
    const float* b1 = (const float*)d_in[3];
    const float* W2 = (const float*)d_in[4];
    const float* b2 = (const float*)d_in[5];
    const float* Ww = (const float*)d_in[6];
    const float* bw = (const float*)d_in[7];
    const float* Wk = (const float*)d_in[8];
    const float* bk = (const float*)d_in[9];
    float* out = (float*)d_out;

    int n  = out_size;
    int n4 = n >> 2;
    int blocks = 148 * 8;                      // persistent, 8 CTAs/SM
    int needed = (n4 + 511) / 512;
    if (needed < 1) needed = 1;
    if (blocks > needed) blocks = needed;

    fused_spline_kernel<<<blocks, 256>>>(x, out, n,
                                         a, W1, b1, W2, b2, Ww, bw, Wk, bk);
}

// round 17
// speedup vs baseline: 1.2089x; 1.0011x over previous
#include <cuda_runtime.h>
#include <math.h>

#define SQ3    1.7320508075688772f
#define IS3    0.57735026918962576451f
#define HI_CLIP (0.99990f * SQ3)

// ---------------------------------------------------------------------------
// Hot-path eval (R13 form, regs-lean): u = xc - 1 (common center), 3-level
// FSEL binary search -> integer idx -> conflict-free 8-entry LDS.128 -> Horner.
// ---------------------------------------------------------------------------
__device__ __forceinline__ float eval_spline(float xv,
                                             float r1, float r2, float r3, float r4,
                                             float r5, float r6, float r7,
                                             const float4* __restrict__ coef)
{
    float xc = fminf(xv, HI_CLIP);            // inputs >= 0
    float u  = xc - 1.0f;                     // common center; parallel to tree
    bool  b2 = xc >= r4;
    float p1 = b2 ? r6 : r2;
    float q1 = b2 ? r5 : r1;                  // depends only on b2
    float q2 = b2 ? r7 : r3;
    bool  b1 = xc >= p1;
    float p0 = b1 ? q2 : q1;
    bool  b0 = xc >= p0;
    int idx = (b2 ? 4 : 0) + (b1 ? 2 : 0) + (b0 ? 1 : 0);
    float4 cf = coef[idx];                    // 8 x 16B = 128B: conflict-free
    return fmaf(fmaf(fmaf(cf.w, u, cf.z), u, cf.y), u, cf.x);
}

// ---------------------------------------------------------------------------
// Single fused persistent kernel (8 CTAs/SM, regs 32). Prologue per CTA
// (float-only): stage weights -> tiny MLP -> softmax/cumsum knots -> symbolic
// de Boor -> float Taylor shift to common center x=1 -> shared coef table.
// Main loop over the 512-aligned region with NO inner predicates.
// ---------------------------------------------------------------------------
__global__ __launch_bounds__(256) void fused_spline_kernel(
        const float* __restrict__ x, float* __restrict__ y, int n,
        const float* __restrict__ a,
        const float* __restrict__ W1, const float* __restrict__ b1,
        const float* __restrict__ W2, const float* __restrict__ b2,
        const float* __restrict__ Ww, const float* __restrict__ bw,
        const float* __restrict__ Wk, const float* __restrict__ bk)
{
    __shared__ float sA[1], sW1[16], sB1[16], sW2[256], sB2[16];
    __shared__ float sWW[144], sBW[9], sWK[112], sBK[7];
    __shared__ float n1[16], n2[16], w9[9], kl7[7];
    __shared__ float t[14], c[10], knx[8];
    __shared__ float4 s_coef[8];          // conflict-free LDS.128 table

    int tid = threadIdx.x;

    // ---- stage all 577 weight scalars (one parallel load round) ----
    if (tid == 0) sA[0] = a[0];
    if (tid < 16) { sW1[tid] = W1[tid]; sB1[tid] = b1[tid]; sB2[tid] = b2[tid]; }
    sW2[tid] = W2[tid];
    if (tid < 144) sWW[tid] = Ww[tid];
    if (tid < 112) sWK[tid] = Wk[tid];
    if (tid >= 128 && tid < 137) sBW[tid - 128] = bw[tid - 128];
    if (tid >= 160 && tid < 167) sBK[tid - 160] = bk[tid - 160];
    __syncthreads();

    // ---- layer 1 ----
    if (tid < 16) n1[tid] = sinf(sA[0] * sW1[tid] + sB1[tid]);
    __syncthreads();

    // ---- layer 2 ----
    if (tid < 16) {
        float s = sB2[tid];
        #pragma unroll
        for (int j = 0; j < 16; j++) s += n1[j] * sW2[j * 16 + tid];
        n2[tid] = sinf(s);
    }
    __syncthreads();

    // ---- heads (two warps in parallel) ----
    if (tid < 9) {
        float s = sBW[tid];
        #pragma unroll
        for (int j = 0; j < 16; j++) s += n2[j] * sWW[j * 9 + tid];
        w9[tid] = s;
    }
    if (tid >= 32 && tid < 39) {
        int m = tid - 32;
        float s = sBK[m];
        #pragma unroll
        for (int j = 0; j < 16; j++) s += n2[j] * sWK[j * 7 + m];
        kl7[m] = s;
    }
    __syncthreads();

    // ---- softmax + cumsum -> knots; padded knot vector & control points ----
    if (tid == 0) {
        float mx = kl7[0];
        #pragma unroll
        for (int m = 1; m < 7; m++) mx = fmaxf(mx, kl7[m]);
        float e[7], ssum = 0.f;
        #pragma unroll
        for (int m = 0; m < 7; m++) { e[m] = expf(kl7[m] - mx); ssum += e[m]; }
        float inv = 1.f / ssum;
        float kk[8]; kk[0] = 0.f;
        float cum = 0.f;
        #pragma unroll
        for (int m = 0; m < 7; m++) { cum += e[m] * inv; kk[m + 1] = cum; }

        t[0] = t[1] = t[2] = 0.f;
        #pragma unroll
        for (int m = 0; m < 8; m++) { t[3 + m] = kk[m]; knx[m] = kk[m] * SQ3; }
        t[11] = t[12] = t[13] = 1.f;
        c[0] = 0.f;
        #pragma unroll
        for (int m = 0; m < 9; m++) c[1 + m] = w9[m];
    }
    __syncthreads();

    // ---- symbolic de Boor per interval (threads 0..7, knot index k = 3..10) ----
    if (tid < 8) {
        int k = tid + 3;
        float tkn = t[k];
        float d[4][4];   // d[j][m]: coefficient of u^m (normalized space)
        #pragma unroll
        for (int j = 0; j < 4; j++) {
            int ci = k + j - 3; if (ci > 9) ci = 9;   // JAX clip-mode gather
            d[j][0] = c[ci]; d[j][1] = d[j][2] = d[j][3] = 0.f;
        }
        #pragma unroll
        for (int r = 1; r <= 3; r++) {
            #pragma unroll
            for (int j = 3; j >= 1; j--) {
                if (j < r) continue;
                float lo = t[k + j - 3];
                float hi = t[k + j + 1 - r];
                float dt = hi - lo;
                float invd = (dt > 0.f) ? (1.f / dt) : 0.f;   // guard empty tail interval
                float a0 = (tkn - lo) * invd;                 // alpha(u) = a0 + invd*u
                float em1 = 0.f;
                float nd[4];
                #pragma unroll
                for (int m = 0; m < 4; m++) {
                    float ee = d[j][m] - d[j - 1][m];
                    nd[m] = d[j - 1][m] + a0 * ee + invd * em1;
                    em1 = ee;
                }
                #pragma unroll
                for (int m = 0; m < 4; m++) d[j][m] = nd[m];
            }
        }
        // x-space coeffs about the interval knot, then FLOAT Taylor shift to
        // common center x = 1.
        float a0 = d[3][0];
        float a1 = d[3][1] * IS3;
        float a2 = d[3][2] * (IS3 * IS3);
        float a3 = d[3][3] * (IS3 * IS3 * IS3);
        float s  = fmaf(-tkn, SQ3, 1.0f);          // center - left_knot_x
        float b3f = a3;
        float b2f = fmaf(3.0f * a3, s, a2);
        float b1f = fmaf(fmaf(3.0f * a3, s, 2.0f * a2), s, a1);
        float b0f = fmaf(fmaf(fmaf(a3, s, a2), s, a1), s, a0);
        s_coef[tid] = make_float4(b0f, b1f, b2f, b3f);
    }
    __syncthreads();

    // interior knots (x-space) in registers for the binary search
    const float r1 = knx[1], r2 = knx[2], r3 = knx[3], r4 = knx[4];
    const float r5 = knx[5], r6 = knx[6], r7 = knx[7];

    // ---- main streaming loop over 512-aligned region: NO predicates ----
    int n4 = n >> 2;
    int main_n4 = n4 & ~511;              // multiple of 512 float4s
    const float4* __restrict__ xin  = (const float4*)x;
    float4* __restrict__       yout = (float4*)y;
    int step = gridDim.x * 512;

    for (int base = blockIdx.x * 512 + tid; base < main_n4; base += step) {
        int i1 = base + 256;              // provably < main_n4

        float4 v0 = xin[base];            // default caching: L2-resident across replays
        float4 v1 = xin[i1];

        float4 o0;
        o0.x = eval_spline(v0.x, r1,r2,r3,r4,r5,r6,r7, s_coef);
        o0.y = eval_spline(v0.y, r1,r2,r3,r4,r5,r6,r7, s_coef);
        o0.z = eval_spline(v0.z, r1,r2,r3,r4,r5,r6,r7, s_coef);
        o0.w = eval_spline(v0.w, r1,r2,r3,r4,r5,r6,r7, s_coef);
        __stcs(yout + base, o0);          // streaming store: don't thrash L2

        float4 o1;
        o1.x = eval_spline(v1.x, r1,r2,r3,r4,r5,r6,r7, s_coef);
        o1.y = eval_spline(v1.y, r1,r2,r3,r4,r5,r6,r7, s_coef);
        o1.z = eval_spline(v1.z, r1,r2,r3,r4,r5,r6,r7, s_coef);
        o1.w = eval_spline(v1.w, r1,r2,r3,r4,r5,r6,r7, s_coef);
        __stcs(yout + i1, o1);
    }

    // ---- tail: remaining float4s [main_n4, n4) + scalar rem, block 0 ----
    if (blockIdx.x == 0) {
        for (int i = main_n4 + tid; i < n4; i += 256) {
            float4 v = xin[i];
            float4 o;
            o.x = eval_spline(v.x, r1,r2,r3,r4,r5,r6,r7, s_coef);
            o.y = eval_spline(v.y, r1,r2,r3,r4,r5,r6,r7, s_coef);
            o.z = eval_spline(v.z, r1,r2,r3,r4,r5,r6,r7, s_coef);
            o.w = eval_spline(v.w, r1,r2,r3,r4,r5,r6,r7, s_coef);
            yout[i] = o;
        }
        int rem = n - (n4 << 2);
        if (tid < rem) {
            int i = (n4 << 2) + tid;
            y[i] = eval_spline(x[i], r1,r2,r3,r4,r5,r6,r7, s_coef);
        }
    }
}

extern "C" void kernel_launch(void* const* d_in, const int* in_sizes, int n_in,
                              void* d_out, int out_size)
{
    const float* x  = (const float*)d_in[0];
    const float* a  = (const float*)d_in[1];
    const float* W1 = (const float*)d_in[2];
    const float* b1 = (const float*)d_in[3];
    const float* W2 = (const float*)d_in[4];
    const float* b2 = (const float*)d_in[5];
    const float* Ww = (const float*)d_in[6];
    const float* bw = (const float*)d_in[7];
    const float* Wk = (const float*)d_in[8];
    const float* bk = (const float*)d_in[9];
    float* out = (float*)d_out;

    int n  = out_size;
    int n4 = n >> 2;
    int blocks = 148 * 8;                      // persistent, 8 CTAs/SM
    int needed = (n4 + 511) / 512;
    if (needed < 1) needed = 1;
    if (blocks > needed) blocks = needed;

    fused_spline_kernel<<<blocks, 256>>>(x, out, n,
                                         a, W1, b1, W2, b2, Ww, bw, Wk, bk);
}